// round 7
// baseline (speedup 1.0000x reference)
#include <cuda_runtime.h>

// Problem constants
#define NB       4
#define TOK      131072          // T*n tokens per batch
#define C        64
#define NROWS    16384           // n
#define SPLITS   128             // split-K blocks per batch
#define TPS      (TOK / SPLITS)  // 1024 tokens per block
#define NGROUPS  2               // split-K sub-groups within a block
#define TPG      (TPS / NGROUPS) // 512 tokens per sub-group
#define STAGE_T  16              // tokens per sub-group per stage
#define NSTAGES  (TPG / STAGE_T) // 32
#define SROWS    (NGROUPS * STAGE_T)  // 32 rows per stage buffer
#define KROW     140             // K-dup row: 128 dup floats + swizzle pads
#define VROW     68              // V row: 64 + swizzle pad
#define KPLANE   (SROWS * KROW)  // 4480 floats
#define BUFW     (KPLANE + SROWS * VROW) // 6656 floats per buffer

#define KV_SMEM_BYTES  (2 * BUFW * 4)               // 53,248
#define OUT_SMEM_BYTES ((C * C + 2 * 128 * VROW) * 4) // 86,016

// Scratch (no allocations allowed)
__device__ float g_partial[(size_t)NB * SPLITS * C * C];    // 8 MB partials [b][s][c][d]
__device__ float g_kv[NB * C * C];                          // [b][c][d]
__device__ float g_sm[NB * C * C];                          // [b][c][d], alpha folded in

typedef unsigned long long u64;

__device__ __forceinline__ u64 fma2(u64 a, u64 b, u64 c) {
    u64 d;
    asm("fma.rn.f32x2 %0, %1, %2, %3;" : "=l"(d) : "l"(a), "l"(b), "l"(c));
    return d;
}
__device__ __forceinline__ u64 add2(u64 a, u64 b) {
    u64 d;
    asm("add.rn.f32x2 %0, %1, %2;" : "=l"(d) : "l"(a), "l"(b));
    return d;
}
__device__ __forceinline__ float2 unpack2(u64 v) {
    float2 r;
    asm("mov.b64 {%0, %1}, %2;" : "=f"(r.x), "=f"(r.y) : "l"(v));
    return r;
}
__device__ __forceinline__ void stcg4(float* p, float4 v) {
    asm volatile("st.global.cg.v4.f32 [%0], {%1,%2,%3,%4};"
                 :: "l"(p), "f"(v.x), "f"(v.y), "f"(v.z), "f"(v.w));
}
__device__ __forceinline__ void cp16(unsigned dst, const float* src) {
    asm volatile("cp.async.ca.shared.global [%0], [%1], 16;" :: "r"(dst), "l"(src));
}
__device__ __forceinline__ void cp_commit() {
    asm volatile("cp.async.commit_group;");
}
template <int N>
__device__ __forceinline__ void cp_wait() {
    asm volatile("cp.async.wait_group %0;" :: "n"(N));
}

// additive bank swizzle: float offset f -> f + (f>>5)*4  (per 32-float segment)
#define KSWZ(f) ((f) + (((f) >> 5) << 2))

// ---------------------------------------------------------------------------
// Kernel A: partial kv_mul.  K stored DUPLICATED ({k,k} pairs) in smem so the
// inner loop has ZERO register-duplication MOVs:
//   per token: 4x LDS.128 (K dup, conflict-free via swizzle) + 1x LDS.128 (V)
//              + 16x FFMA2.
// 256 threads = 2 split-K sub-groups of 128; thread grid 8(c) x 16(d),
// tile 8c x 4d -> acc[8][2] f32x2 (32 regs).  ~90 regs total -> occ 2
// (4 warps/SMSP) with __launch_bounds__(256,2), no spills.
// LDG.128 -> regs -> STS.128 double buffering, one barrier per 16-token stage.
// ---------------------------------------------------------------------------
__global__ __launch_bounds__(256, 2) void kv_partial_kernel(
    const float* __restrict__ Kg, const float* __restrict__ Vg)
{
    extern __shared__ __align__(16) float s[];

    const int b   = blockIdx.y;
    const int sp  = blockIdx.x;
    const int tid = threadIdx.x;
    const int g   = tid >> 7;              // sub-group 0..1
    const int gt  = tid & 127;
    const int cg  = gt >> 4;               // 0..7  -> c0 = cg*8
    const int dg  = gt & 15;               // 0..15 -> d0 = dg*4
    const int kofs = KSWZ(cg * 16);        // K-dup load base within row
    const int vofs = dg * 4 + ((dg >> 3) << 2);

    // chunk mapping: 1024 16B-chunks per stage (2 arrays x 32 rows x 16),
    // 4 per thread; j=0,1 -> K (duplicated store), j=2,3 -> V.
    int offw[4];   // gmem float offset (stage 0)
    int kdst[2];   // K dup smem float offset (within K plane)
    int vdst[2];   // V smem float offset (within V plane)
    #pragma unroll
    for (int j = 0; j < 4; ++j) {
        int ch  = tid + j * 256;           // 0..1023
        int wi  = ch & 511;
        int row = wi >> 4;                 // 0..31
        int c4  = wi & 15;
        int gr  = row >> 4, tl = row & 15;
        offw[j] = (gr * TPG + tl) * C + c4 * 4;
        if (j < 2) kdst[j]     = row * KROW + KSWZ(c4 * 8);
        else       vdst[j - 2] = row * VROW + c4 * 4 + ((c4 >> 3) << 2);
    }
    const float* Kbase = Kg + ((size_t)b * TOK + (size_t)sp * TPS) * C;
    const float* Vbase = Vg + ((size_t)b * TOK + (size_t)sp * TPS) * C;

    float4 pf[4];
    // prologue: stage 0 -> regs -> buf0 ; stage 1 -> regs
    pf[0] = *(const float4*)(Kbase + offw[0]);
    pf[1] = *(const float4*)(Kbase + offw[1]);
    pf[2] = *(const float4*)(Vbase + offw[2]);
    pf[3] = *(const float4*)(Vbase + offw[3]);
    #pragma unroll
    for (int j = 0; j < 2; ++j) {
        float4 v = pf[j];
        *(float4*)&s[kdst[j]]     = make_float4(v.x, v.x, v.y, v.y);
        *(float4*)&s[kdst[j] + 4] = make_float4(v.z, v.z, v.w, v.w);
        *(float4*)&s[KPLANE + vdst[j]] = pf[j + 2];
    }
    pf[0] = *(const float4*)(Kbase + offw[0] + STAGE_T * C);
    pf[1] = *(const float4*)(Kbase + offw[1] + STAGE_T * C);
    pf[2] = *(const float4*)(Vbase + offw[2] + STAGE_T * C);
    pf[3] = *(const float4*)(Vbase + offw[3] + STAGE_T * C);
    __syncthreads();

    u64 acc[8][2];   // [c within tile][d-pair]
    #pragma unroll
    for (int i = 0; i < 8; ++i) { acc[i][0] = 0ull; acc[i][1] = 0ull; }

    #pragma unroll 1
    for (int it = 0; it < NSTAGES; ++it) {
        // stash stage it+1 (in regs) into the buffer freed by stage it-1
        if (it + 1 < NSTAGES) {
            float* dB = &s[((it + 1) & 1) * BUFW];
            #pragma unroll
            for (int j = 0; j < 2; ++j) {
                float4 v = pf[j];
                *(float4*)&dB[kdst[j]]     = make_float4(v.x, v.x, v.y, v.y);
                *(float4*)&dB[kdst[j] + 4] = make_float4(v.z, v.z, v.w, v.w);
                *(float4*)&dB[KPLANE + vdst[j]] = pf[j + 2];
            }
        }
        // prefetch stage it+2 into regs
        if (it + 2 < NSTAGES) {
            const int adv = (it + 2) * STAGE_T * C;
            pf[0] = *(const float4*)(Kbase + offw[0] + adv);
            pf[1] = *(const float4*)(Kbase + offw[1] + adv);
            pf[2] = *(const float4*)(Vbase + offw[2] + adv);
            pf[3] = *(const float4*)(Vbase + offw[3] + adv);
        }

        const float* kb_ = &s[(it & 1) * BUFW];
        const float* vb_ = kb_ + KPLANE;
        #pragma unroll
        for (int t = 0; t < STAGE_T; ++t) {
            const int r = g * STAGE_T + t;
            const float* kp = &kb_[r * KROW + kofs];
            ulonglong2 k01 = *(const ulonglong2*)(kp);      // {k0,k0},{k1,k1}
            ulonglong2 k23 = *(const ulonglong2*)(kp + 4);
            ulonglong2 k45 = *(const ulonglong2*)(kp + 8);
            ulonglong2 k67 = *(const ulonglong2*)(kp + 12);
            ulonglong2 vv  = *(const ulonglong2*)&vb_[r * VROW + vofs]; // {v0,v1},{v2,v3}
            acc[0][0] = fma2(k01.x, vv.x, acc[0][0]);
            acc[0][1] = fma2(k01.x, vv.y, acc[0][1]);
            acc[1][0] = fma2(k01.y, vv.x, acc[1][0]);
            acc[1][1] = fma2(k01.y, vv.y, acc[1][1]);
            acc[2][0] = fma2(k23.x, vv.x, acc[2][0]);
            acc[2][1] = fma2(k23.x, vv.y, acc[2][1]);
            acc[3][0] = fma2(k23.y, vv.x, acc[3][0]);
            acc[3][1] = fma2(k23.y, vv.y, acc[3][1]);
            acc[4][0] = fma2(k45.x, vv.x, acc[4][0]);
            acc[4][1] = fma2(k45.x, vv.y, acc[4][1]);
            acc[5][0] = fma2(k45.y, vv.x, acc[5][0]);
            acc[5][1] = fma2(k45.y, vv.y, acc[5][1]);
            acc[6][0] = fma2(k67.x, vv.x, acc[6][0]);
            acc[6][1] = fma2(k67.x, vv.y, acc[6][1]);
            acc[7][0] = fma2(k67.y, vv.x, acc[7][0]);
            acc[7][1] = fma2(k67.y, vv.y, acc[7][1]);
        }
        __syncthreads();   // compute of it done everywhere; STS of it+1 drained
    }

    // deterministic in-block split-K reduction: g1 -> smem -> g0 adds
    u64* sred = (u64*)s;   // 128 thr * 16 u64 = 16 KB (buffer 0, free now)
    if (g == 1) {
        u64* dst = &sred[gt * 16];
        #pragma unroll
        for (int i = 0; i < 8; ++i) {
            dst[i * 2]     = acc[i][0];
            dst[i * 2 + 1] = acc[i][1];
        }
    }
    __syncthreads();
    if (g == 0) {
        const u64* s2 = &sred[gt * 16];
        #pragma unroll
        for (int i = 0; i < 8; ++i) {
            acc[i][0] = add2(acc[i][0], s2[i * 2]);
            acc[i][1] = add2(acc[i][1], s2[i * 2 + 1]);
        }
        float* outp = &g_partial[((size_t)(b * SPLITS + sp)) * (C * C)];
        const int c0 = cg * 8, d0 = dg * 4;
        #pragma unroll
        for (int i = 0; i < 8; ++i) {
            float2 p0 = unpack2(acc[i][0]);
            float2 p1 = unpack2(acc[i][1]);
            stcg4(&outp[(c0 + i) * C + d0], make_float4(p0.x, p0.y, p1.x, p1.y));
        }
    }
}

// ---------------------------------------------------------------------------
// Kernel B: deterministic split reduction (float4, fixed order).
// ---------------------------------------------------------------------------
__global__ __launch_bounds__(128, 1) void kv_reduce_kernel()
{
    int q = blockIdx.x * 128 + threadIdx.x;   // 0..4095 float4 index
    int b  = q >> 10;
    int e4 = q & 1023;
    const float4* p = (const float4*)&g_partial[(size_t)b * SPLITS * (C * C)] + e4;
    float4 s0 = make_float4(0.f,0.f,0.f,0.f), s1 = s0, s2 = s0, s3 = s0;
    float4 s4 = s0, s5 = s0, s6 = s0, s7 = s0;
    #pragma unroll 2
    for (int i = 0; i < SPLITS; i += 8) {
        float4 t0 = p[(size_t)(i    ) * 1024];
        float4 t1 = p[(size_t)(i + 1) * 1024];
        float4 t2 = p[(size_t)(i + 2) * 1024];
        float4 t3 = p[(size_t)(i + 3) * 1024];
        float4 t4 = p[(size_t)(i + 4) * 1024];
        float4 t5 = p[(size_t)(i + 5) * 1024];
        float4 t6 = p[(size_t)(i + 6) * 1024];
        float4 t7 = p[(size_t)(i + 7) * 1024];
        s0.x += t0.x; s0.y += t0.y; s0.z += t0.z; s0.w += t0.w;
        s1.x += t1.x; s1.y += t1.y; s1.z += t1.z; s1.w += t1.w;
        s2.x += t2.x; s2.y += t2.y; s2.z += t2.z; s2.w += t2.w;
        s3.x += t3.x; s3.y += t3.y; s3.z += t3.z; s3.w += t3.w;
        s4.x += t4.x; s4.y += t4.y; s4.z += t4.z; s4.w += t4.w;
        s5.x += t5.x; s5.y += t5.y; s5.z += t5.z; s5.w += t5.w;
        s6.x += t6.x; s6.y += t6.y; s6.z += t6.z; s6.w += t6.w;
        s7.x += t7.x; s7.y += t7.y; s7.z += t7.z; s7.w += t7.w;
    }
    float4 r;
    r.x = ((s0.x + s1.x) + (s2.x + s3.x)) + ((s4.x + s5.x) + (s6.x + s7.x));
    r.y = ((s0.y + s1.y) + (s2.y + s3.y)) + ((s4.y + s5.y) + (s6.y + s7.y));
    r.z = ((s0.z + s1.z) + (s2.z + s3.z)) + ((s4.z + s5.z) + (s6.z + s7.z));
    r.w = ((s0.w + s1.w) + (s2.w + s3.w)) + ((s4.w + s5.w) + (s6.w + s7.w));
    ((float4*)g_kv)[q] = r;
}

// ---------------------------------------------------------------------------
// Kernel C: softmax over the C axis (column-strided), alpha folded in.
// ---------------------------------------------------------------------------
__global__ void softmax_kernel(const float* __restrict__ alpha)
{
    int tid = threadIdx.x;
    int b = tid >> 6;
    int d = tid & 63;
    const float* in  = &g_kv[b * (C * C) + d];
    float*       out = &g_sm[b * (C * C) + d];

    float v[C];
    float m = -3.402823466e38f;
    #pragma unroll
    for (int c = 0; c < C; ++c) { v[c] = in[c * C]; m = fmaxf(m, v[c]); }
    float sum = 0.f;
    #pragma unroll
    for (int c = 0; c < C; ++c) { v[c] = expf(v[c] - m); sum += v[c]; }
    float sc = alpha[0] / sum;
    #pragma unroll
    for (int c = 0; c < C; ++c) out[c * C] = v[c] * sc;
}

// ---------------------------------------------------------------------------
// Kernel D: out[b,r,d] = sum_c key_cur[b,r,c] * sm[b,c,d] + val_cur.
// 128 threads, 128 rows per block; thread = 8 rows (strided 16) x 8 d.
// val_cur prefetched into smem via cp.async at kernel start so the epilogue
// tail has no long-latency LDGs.
// ---------------------------------------------------------------------------
__global__ __launch_bounds__(128, 2) void out_kernel(
    const float* __restrict__ key_cur, const float* __restrict__ val_cur,
    float* __restrict__ out)
{
    extern __shared__ __align__(16) float s[];
    float* s_sm  = s;                      // [c][d] 64x64, 16 KB
    float* s_key = s + C * C;              // [128][VROW]
    float* s_val = s + C * C + 128 * VROW; // [128][VROW]

    const int b   = blockIdx.y;
    const int rb  = blockIdx.x;       // 0..127 (128 rows each)
    const int tid = threadIdx.x;
    const size_t row_base = (size_t)b * NROWS + (size_t)rb * 128;

    // val_cur prefetch: 2048 chunks / 128 thr = 16 each (async, waited at end)
    #pragma unroll
    for (int j = 0; j < 16; ++j) {
        int ch  = j * 128 + tid;
        int row = ch >> 4, c4 = ch & 15;
        cp16((unsigned)__cvta_generic_to_shared(&s_val[row * VROW + c4 * 4]),
             &val_cur[(row_base + row) * C + c4 * 4]);
    }
    cp_commit();

    // sm matrix (alpha folded): 1024 float4 / 128 thr = 8 each
    const float* smg = &g_sm[b * (C * C)];
    #pragma unroll
    for (int j = 0; j < 8; ++j) {
        int q = j * 128 + tid;
        *(float4*)&s_sm[q * 4] = *(const float4*)&smg[q * 4];
    }
    // keys: 128 rows x 16 chunks = 2048 float4 / 128 thr = 16 each
    #pragma unroll
    for (int j = 0; j < 16; ++j) {
        int ch  = j * 128 + tid;
        int row = ch >> 4, c4 = ch & 15;
        *(float4*)&s_key[row * VROW + c4 * 4] =
            *(const float4*)&key_cur[(row_base + row) * C + c4 * 4];
    }
    __syncthreads();

    const int rg = tid >> 3;          // 0..15: rows rg, rg+16, ..., rg+112
    const int d0 = (tid & 7) * 8;

    u64 acc[8][4];
    #pragma unroll
    for (int i = 0; i < 8; ++i)
        #pragma unroll
        for (int p = 0; p < 4; ++p) acc[i][p] = 0ull;

    #pragma unroll 2
    for (int cq = 0; cq < 16; ++cq) {
        float4 kq[8];
        #pragma unroll
        for (int i = 0; i < 8; ++i)
            kq[i] = *(const float4*)&s_key[(rg + 16 * i) * VROW + cq * 4];
        #pragma unroll
        for (int cc = 0; cc < 4; ++cc) {
            ulonglong2 sa = *(const ulonglong2*)&s_sm[(cq * 4 + cc) * C + d0];
            ulonglong2 sb = *(const ulonglong2*)&s_sm[(cq * 4 + cc) * C + d0 + 4];
            #pragma unroll
            for (int i = 0; i < 8; ++i) {
                float kc = (cc == 0) ? kq[i].x : (cc == 1) ? kq[i].y
                         : (cc == 2) ? kq[i].z : kq[i].w;
                u64 kd;
                asm("mov.b64 %0, {%1, %1};" : "=l"(kd) : "f"(kc));
                acc[i][0] = fma2(kd, sa.x, acc[i][0]);
                acc[i][1] = fma2(kd, sa.y, acc[i][1]);
                acc[i][2] = fma2(kd, sb.x, acc[i][2]);
                acc[i][3] = fma2(kd, sb.y, acc[i][3]);
            }
        }
    }

    cp_wait<0>();
    __syncthreads();   // val_cur fully staged for all threads

    #pragma unroll
    for (int i = 0; i < 8; ++i) {
        const int row = rg + 16 * i;
        float4 v0 = *(const float4*)&s_val[row * VROW + d0];
        float4 v1 = *(const float4*)&s_val[row * VROW + d0 + 4];
        size_t base = (row_base + row) * C + d0;
        float2 p0 = unpack2(acc[i][0]), p1 = unpack2(acc[i][1]);
        float2 p2 = unpack2(acc[i][2]), p3 = unpack2(acc[i][3]);
        *(float4*)&out[base]     = make_float4(p0.x + v0.x, p0.y + v0.y,
                                               p1.x + v0.z, p1.y + v0.w);
        *(float4*)&out[base + 4] = make_float4(p2.x + v1.x, p2.y + v1.y,
                                               p3.x + v1.z, p3.y + v1.w);
    }
}

// ---------------------------------------------------------------------------
extern "C" void kernel_launch(void* const* d_in, const int* in_sizes, int n_in,
                              void* d_out, int out_size)
{
    const float* key_mem = (const float*)d_in[0];
    const float* val_mem = (const float*)d_in[1];
    const float* key_cur = (const float*)d_in[2];
    const float* val_cur = (const float*)d_in[3];
    const float* alpha   = (const float*)d_in[4];
    float* out = (float*)d_out;

    cudaFuncSetAttribute(kv_partial_kernel,
                         cudaFuncAttributeMaxDynamicSharedMemorySize, KV_SMEM_BYTES);
    cudaFuncSetAttribute(out_kernel,
                         cudaFuncAttributeMaxDynamicSharedMemorySize, OUT_SMEM_BYTES);

    kv_partial_kernel<<<dim3(SPLITS, NB), 256, KV_SMEM_BYTES>>>(key_mem, val_mem);
    kv_reduce_kernel<<<32, 128>>>();
    softmax_kernel<<<1, 256>>>(alpha);
    out_kernel<<<dim3(NROWS / 128, NB), 128, OUT_SMEM_BYTES>>>(key_cur, val_cur, out);
}

// round 9
// speedup vs baseline: 1.5449x; 1.5449x over previous
#include <cuda_runtime.h>
#include <cstdint>

// ---------------------------------------------------------------------------
// Problem constants
#define NB       4
#define TOK      131072          // T*n tokens per batch
#define C        64
#define NROWS    16384           // n
#define SPLITS   128             // split-K blocks per batch
#define TPS      (TOK / SPLITS)  // 1024 tokens per block
#define STAGE_T  32              // tokens per stage
#define NSTAGES  (TPS / STAGE_T) // 32
#define RPK      72              // padded row (kv staging): 8*lr+lq -> all banks
#define PLANE    (STAGE_T * RPK) // floats per array plane (2304)
#define BUFW     (2 * PLANE)     // floats per buffer (K+V)
#define RP       68              // padded row (out_kernel)

#define KV_SMEM_BYTES  (2 * BUFW * 4)              // 36,864 B
#define OUT_SMEM_BYTES ((C * C + 128 * RP) * 4)    // 51,200 B

// Scratch (no allocations allowed)
__device__ float g_partial[(size_t)NB * SPLITS * C * C];    // 8 MB [b][s][c][d]
__device__ float g_kv[NB * C * C];                          // [b][c][d]
__device__ float g_sm[NB * C * C];                          // [b][c][d], alpha folded

typedef unsigned long long u64;

// ---- scalar helpers ----
__device__ __forceinline__ u64 fma2(u64 a, u64 b, u64 c) {
    u64 d;
    asm("fma.rn.f32x2 %0, %1, %2, %3;" : "=l"(d) : "l"(a), "l"(b), "l"(c));
    return d;
}
__device__ __forceinline__ float2 unpack2(u64 v) {
    float2 r;
    asm("mov.b64 {%0, %1}, %2;" : "=f"(r.x), "=f"(r.y) : "l"(v));
    return r;
}
__device__ __forceinline__ void stcg2(float* p, float x, float y) {
    asm volatile("st.global.cg.v2.f32 [%0], {%1,%2};" :: "l"(p), "f"(x), "f"(y));
}

// tf32 split: hi = exact-tf32 truncation, lo = residual (HW rounds lo to tf32)
__device__ __forceinline__ uint32_t tf32hi(float x) {
    return __float_as_uint(x) & 0xffffe000u;
}
__device__ __forceinline__ uint32_t tf32lo(float x, uint32_t hi) {
    return __float_as_uint(x - __uint_as_float(hi));
}

// m16n8k8 tf32 HMMA: D += A x B  (A row-major 16x8, B col-frag 8x8, fp32 acc)
__device__ __forceinline__ void mma8(float* d, const uint32_t* a, const uint32_t* b) {
    asm volatile(
        "mma.sync.aligned.m16n8k8.row.col.f32.tf32.tf32.f32 "
        "{%0,%1,%2,%3}, {%4,%5,%6,%7}, {%8,%9}, {%0,%1,%2,%3};"
        : "+f"(d[0]), "+f"(d[1]), "+f"(d[2]), "+f"(d[3])
        : "r"(a[0]), "r"(a[1]), "r"(a[2]), "r"(a[3]), "r"(b[0]), "r"(b[1]));
}

// ---------------------------------------------------------------------------
// Kernel A: partial kv_mul on HMMA (mma.sync tf32, 3-product split).
// kv[c][d] = sum_t K[t][c] * V[t][d]  -> A = K^T (m=c=16/warp), B = V (n=d).
// 256 threads = 8 warps in 4(c) x 2(d) grid; warp tile 16c x 32d = acc[4][4].
// Per 8-token chunk: 4 A-loads + 8 B-loads (LDS.32, conflict-free via RPK=72)
// + tf32 splits + 12 HMMAs (4 n-chunks x {hh, hl, lh}).
// Staging: LDG.128 -> regs -> STS.128 double buffer, 32-token stages (round-6).
// Each warp owns a disjoint output tile -> no cross-warp reduction.
// ---------------------------------------------------------------------------
__global__ __launch_bounds__(256, 2) void kv_partial_kernel(
    const float* __restrict__ Kg, const float* __restrict__ Vg)
{
    extern __shared__ __align__(16) float s[];

    const int b   = blockIdx.y;
    const int sp  = blockIdx.x;
    const int tid = threadIdx.x;
    const int w   = tid >> 5;
    const int l   = tid & 31;
    const int lr  = l & 3;          // k-row within fragment
    const int lq  = l >> 2;         // group id
    const int c0  = (w & 3) * 16;   // warp c origin
    const int d0  = (w >> 2) * 32;  // warp d origin

    // staging chunk mapping: 1024 16B-chunks per stage, 4 per thread
    // j=0,1 -> K plane; j=2,3 -> V plane
    int offw[4], dstw[4];
    #pragma unroll
    for (int j = 0; j < 4; ++j) {
        int ch  = tid + j * 256;    // 0..1023
        int arr = ch >> 9;
        int wi  = ch & 511;
        int row = wi >> 4;          // token 0..31
        int c4  = wi & 15;
        offw[j] = row * C + c4 * 4;
        dstw[j] = arr * PLANE + row * RPK + c4 * 4;
    }
    const float* Kbase = Kg + ((size_t)b * TOK + (size_t)sp * TPS) * C;
    const float* Vbase = Vg + ((size_t)b * TOK + (size_t)sp * TPS) * C;

    float4 pf[4];
    // prologue: stage 0 -> regs -> buf0 ; stage 1 -> regs
    pf[0] = *(const float4*)(Kbase + offw[0]);
    pf[1] = *(const float4*)(Kbase + offw[1]);
    pf[2] = *(const float4*)(Vbase + offw[2]);
    pf[3] = *(const float4*)(Vbase + offw[3]);
    #pragma unroll
    for (int j = 0; j < 4; ++j) *(float4*)&s[dstw[j]] = pf[j];
    pf[0] = *(const float4*)(Kbase + offw[0] + STAGE_T * C);
    pf[1] = *(const float4*)(Kbase + offw[1] + STAGE_T * C);
    pf[2] = *(const float4*)(Vbase + offw[2] + STAGE_T * C);
    pf[3] = *(const float4*)(Vbase + offw[3] + STAGE_T * C);
    __syncthreads();

    float acc[4][4];                 // [n-chunk][frag reg]
    #pragma unroll
    for (int i = 0; i < 4; ++i)
        #pragma unroll
        for (int j = 0; j < 4; ++j) acc[i][j] = 0.f;

    #pragma unroll 1
    for (int it = 0; it < NSTAGES; ++it) {
        // stash stage it+1 into the buffer freed by stage it-1
        if (it + 1 < NSTAGES) {
            float* dB = &s[((it + 1) & 1) * BUFW];
            #pragma unroll
            for (int j = 0; j < 4; ++j) *(float4*)&dB[dstw[j]] = pf[j];
        }
        // prefetch stage it+2 into regs
        if (it + 2 < NSTAGES) {
            const int adv = (it + 2) * STAGE_T * C;
            pf[0] = *(const float4*)(Kbase + offw[0] + adv);
            pf[1] = *(const float4*)(Kbase + offw[1] + adv);
            pf[2] = *(const float4*)(Vbase + offw[2] + adv);
            pf[3] = *(const float4*)(Vbase + offw[3] + adv);
        }

        const float* kp = &s[(it & 1) * BUFW];          // K plane [t][RPK]
        const float* vp = kp + PLANE;                   // V plane
        #pragma unroll
        for (int kc = 0; kc < 4; ++kc) {
            const int t0 = kc * 8;
            // A fragment: A[row][col] = K[t0+col][c0+row]
            const float* ka = &kp[(t0 + lr) * RPK + c0 + lq];
            float a0 = ka[0];
            float a1 = ka[8];
            float a2 = ka[4 * RPK];
            float a3 = ka[4 * RPK + 8];
            uint32_t ahi[4], alo[4];
            ahi[0] = tf32hi(a0); alo[0] = tf32lo(a0, ahi[0]);
            ahi[1] = tf32hi(a1); alo[1] = tf32lo(a1, ahi[1]);
            ahi[2] = tf32hi(a2); alo[2] = tf32lo(a2, ahi[2]);
            ahi[3] = tf32hi(a3); alo[3] = tf32lo(a3, ahi[3]);

            const float* vb = &vp[(t0 + lr) * RPK + d0 + lq];
            #pragma unroll
            for (int nn = 0; nn < 4; ++nn) {
                float b0 = vb[nn * 8];
                float b1 = vb[nn * 8 + 4 * RPK];
                uint32_t bhi[2], blo[2];
                bhi[0] = tf32hi(b0); blo[0] = tf32lo(b0, bhi[0]);
                bhi[1] = tf32hi(b1); blo[1] = tf32lo(b1, bhi[1]);
                mma8(acc[nn], ahi, bhi);
                mma8(acc[nn], ahi, blo);
                mma8(acc[nn], alo, bhi);
            }
        }
        __syncthreads();   // compute of it done everywhere; STS of it+1 drained
    }

    // epilogue: D fragment -> g_partial[b][sp][c][d]  (disjoint per warp)
    float* outp = &g_partial[((size_t)(b * SPLITS + sp)) * (C * C)];
    const int row0 = c0 + lq;
    const int row1 = row0 + 8;
    #pragma unroll
    for (int nn = 0; nn < 4; ++nn) {
        const int col = d0 + nn * 8 + 2 * lr;
        stcg2(&outp[row0 * C + col], acc[nn][0], acc[nn][1]);
        stcg2(&outp[row1 * C + col], acc[nn][2], acc[nn][3]);
    }
}

// ---------------------------------------------------------------------------
// Kernel B: deterministic split reduction (float4, fixed order).
// ---------------------------------------------------------------------------
__global__ __launch_bounds__(128, 1) void kv_reduce_kernel()
{
    int q = blockIdx.x * 128 + threadIdx.x;   // 0..4095 float4 index
    int b  = q >> 10;
    int e4 = q & 1023;
    const float4* p = (const float4*)&g_partial[(size_t)b * SPLITS * (C * C)] + e4;
    float4 s0 = make_float4(0.f,0.f,0.f,0.f), s1 = s0, s2 = s0, s3 = s0;
    float4 s4 = s0, s5 = s0, s6 = s0, s7 = s0;
    #pragma unroll 2
    for (int i = 0; i < SPLITS; i += 8) {
        float4 t0 = p[(size_t)(i    ) * 1024];
        float4 t1 = p[(size_t)(i + 1) * 1024];
        float4 t2 = p[(size_t)(i + 2) * 1024];
        float4 t3 = p[(size_t)(i + 3) * 1024];
        float4 t4 = p[(size_t)(i + 4) * 1024];
        float4 t5 = p[(size_t)(i + 5) * 1024];
        float4 t6 = p[(size_t)(i + 6) * 1024];
        float4 t7 = p[(size_t)(i + 7) * 1024];
        s0.x += t0.x; s0.y += t0.y; s0.z += t0.z; s0.w += t0.w;
        s1.x += t1.x; s1.y += t1.y; s1.z += t1.z; s1.w += t1.w;
        s2.x += t2.x; s2.y += t2.y; s2.z += t2.z; s2.w += t2.w;
        s3.x += t3.x; s3.y += t3.y; s3.z += t3.z; s3.w += t3.w;
        s4.x += t4.x; s4.y += t4.y; s4.z += t4.z; s4.w += t4.w;
        s5.x += t5.x; s5.y += t5.y; s5.z += t5.z; s5.w += t5.w;
        s6.x += t6.x; s6.y += t6.y; s6.z += t6.z; s6.w += t6.w;
        s7.x += t7.x; s7.y += t7.y; s7.z += t7.z; s7.w += t7.w;
    }
    float4 r;
    r.x = ((s0.x + s1.x) + (s2.x + s3.x)) + ((s4.x + s5.x) + (s6.x + s7.x));
    r.y = ((s0.y + s1.y) + (s2.y + s3.y)) + ((s4.y + s5.y) + (s6.y + s7.y));
    r.z = ((s0.z + s1.z) + (s2.z + s3.z)) + ((s4.z + s5.z) + (s6.z + s7.z));
    r.w = ((s0.w + s1.w) + (s2.w + s3.w)) + ((s4.w + s5.w) + (s6.w + s7.w));
    ((float4*)g_kv)[q] = r;
}

// ---------------------------------------------------------------------------
// Kernel C: softmax over the C axis (column-strided), alpha folded in.
// ---------------------------------------------------------------------------
__global__ void softmax_kernel(const float* __restrict__ alpha)
{
    int tid = threadIdx.x;
    int b = tid >> 6;
    int d = tid & 63;
    const float* in  = &g_kv[b * (C * C) + d];
    float*       out = &g_sm[b * (C * C) + d];

    float v[C];
    float m = -3.402823466e38f;
    #pragma unroll
    for (int c = 0; c < C; ++c) { v[c] = in[c * C]; m = fmaxf(m, v[c]); }
    float sum = 0.f;
    #pragma unroll
    for (int c = 0; c < C; ++c) { v[c] = expf(v[c] - m); sum += v[c]; }
    float sc = alpha[0] / sum;
    #pragma unroll
    for (int c = 0; c < C; ++c) out[c * C] = v[c] * sc;
}

// ---------------------------------------------------------------------------
// Kernel D: out[b,r,d] = sum_c key_cur[b,r,c] * sm[b,c,d] + val_cur.
// (round-6 best: 128 thr, 128 rows/block, 8 rows x 8 d per thread, 21 us)
// ---------------------------------------------------------------------------
__global__ __launch_bounds__(128, 2) void out_kernel(
    const float* __restrict__ key_cur, const float* __restrict__ val_cur,
    float* __restrict__ out)
{
    extern __shared__ __align__(16) float s[];
    float* s_sm  = s;                 // [c][d] 64x64, 16 KB
    float* s_key = s + C * C;         // [128][RP]

    const int b   = blockIdx.y;
    const int rb  = blockIdx.x;       // 0..127 (128 rows each)
    const int tid = threadIdx.x;
    const size_t row_base = (size_t)b * NROWS + (size_t)rb * 128;

    const float* smg = &g_sm[b * (C * C)];
    #pragma unroll
    for (int j = 0; j < 8; ++j) {
        int q = j * 128 + tid;
        *(float4*)&s_sm[q * 4] = *(const float4*)&smg[q * 4];
    }
    #pragma unroll
    for (int j = 0; j < 16; ++j) {
        int ch  = j * 128 + tid;
        int row = ch >> 4, c4 = ch & 15;
        *(float4*)&s_key[row * RP + c4 * 4] =
            *(const float4*)&key_cur[(row_base + row) * C + c4 * 4];
    }
    __syncthreads();

    const int rg = tid >> 3;          // rows rg, rg+16, ..., rg+112
    const int d0 = (tid & 7) * 8;

    u64 acc[8][4];
    #pragma unroll
    for (int i = 0; i < 8; ++i)
        #pragma unroll
        for (int p = 0; p < 4; ++p) acc[i][p] = 0ull;

    #pragma unroll 2
    for (int cq = 0; cq < 16; ++cq) {
        float4 kq[8];
        #pragma unroll
        for (int i = 0; i < 8; ++i)
            kq[i] = *(const float4*)&s_key[(rg + 16 * i) * RP + cq * 4];
        #pragma unroll
        for (int cc = 0; cc < 4; ++cc) {
            ulonglong2 sa = *(const ulonglong2*)&s_sm[(cq * 4 + cc) * C + d0];
            ulonglong2 sbv = *(const ulonglong2*)&s_sm[(cq * 4 + cc) * C + d0 + 4];
            #pragma unroll
            for (int i = 0; i < 8; ++i) {
                float kc = (cc == 0) ? kq[i].x : (cc == 1) ? kq[i].y
                         : (cc == 2) ? kq[i].z : kq[i].w;
                u64 kd;
                asm("mov.b64 %0, {%1, %1};" : "=l"(kd) : "f"(kc));
                acc[i][0] = fma2(kd, sa.x, acc[i][0]);
                acc[i][1] = fma2(kd, sa.y, acc[i][1]);
                acc[i][2] = fma2(kd, sbv.x, acc[i][2]);
                acc[i][3] = fma2(kd, sbv.y, acc[i][3]);
            }
        }
    }

    #pragma unroll
    for (int i = 0; i < 8; ++i) {
        size_t base = (row_base + rg + 16 * i) * C + d0;
        float4 v0 = *(const float4*)&val_cur[base];
        float4 v1 = *(const float4*)&val_cur[base + 4];
        float2 p0 = unpack2(acc[i][0]), p1 = unpack2(acc[i][1]);
        float2 p2 = unpack2(acc[i][2]), p3 = unpack2(acc[i][3]);
        *(float4*)&out[base]     = make_float4(p0.x + v0.x, p0.y + v0.y,
                                               p1.x + v0.z, p1.y + v0.w);
        *(float4*)&out[base + 4] = make_float4(p2.x + v1.x, p2.y + v1.y,
                                               p3.x + v1.z, p3.y + v1.w);
    }
}

// ---------------------------------------------------------------------------
extern "C" void kernel_launch(void* const* d_in, const int* in_sizes, int n_in,
                              void* d_out, int out_size)
{
    const float* key_mem = (const float*)d_in[0];
    const float* val_mem = (const float*)d_in[1];
    const float* key_cur = (const float*)d_in[2];
    const float* val_cur = (const float*)d_in[3];
    const float* alpha   = (const float*)d_in[4];
    float* out = (float*)d_out;

    cudaFuncSetAttribute(kv_partial_kernel,
                         cudaFuncAttributeMaxDynamicSharedMemorySize, KV_SMEM_BYTES);
    cudaFuncSetAttribute(out_kernel,
                         cudaFuncAttributeMaxDynamicSharedMemorySize, OUT_SMEM_BYTES);

    kv_partial_kernel<<<dim3(SPLITS, NB), 256, KV_SMEM_BYTES>>>(key_mem, val_mem);
    kv_reduce_kernel<<<32, 128>>>();
    softmax_kernel<<<1, 256>>>(alpha);
    out_kernel<<<dim3(NROWS / 128, NB), 128, OUT_SMEM_BYTES>>>(key_cur, val_cur, out);
}

// round 10
// speedup vs baseline: 1.9314x; 1.2502x over previous
#include <cuda_runtime.h>
#include <cuda_fp16.h>
#include <cstdint>

// ---------------------------------------------------------------------------
// Problem constants
#define NB       4
#define TOK      131072          // T*n tokens per batch
#define C        64
#define NROWS    16384           // n
#define SPLITS   128             // split-K blocks per batch
#define TPS      (TOK / SPLITS)  // 1024 tokens per block
#define STAGE_T  32              // tokens per stage
#define NSTAGES  (TPS / STAGE_T) // 32
#define RPH      72              // plane row stride in u32 (8*lr+lq -> all banks)
#define PLANEU   (16 * RPH)      // u32 per plane (16 token-pairs x 72)
#define BUFU     (4 * PLANEU)    // u32 per buffer (KH0,KH1,VH0,VH1)
#define RP       68              // padded row (out_kernel)

#define KV_SMEM_BYTES  (2 * BUFU * 4)              // 36,864 B
#define OUT_SMEM_BYTES ((C * C + 128 * RP) * 4)    // 51,200 B

// Scratch (no allocations allowed)
__device__ float g_partial[(size_t)NB * SPLITS * C * C];    // 8 MB [b][s][c][d]
__device__ float g_kv[NB * C * C];                          // [b][c][d]
__device__ float g_sm[NB * C * C];                          // [b][c][d], alpha folded

typedef unsigned long long u64;

// ---- scalar helpers ----
__device__ __forceinline__ u64 fma2(u64 a, u64 b, u64 c) {
    u64 d;
    asm("fma.rn.f32x2 %0, %1, %2, %3;" : "=l"(d) : "l"(a), "l"(b), "l"(c));
    return d;
}
__device__ __forceinline__ float2 unpack2(u64 v) {
    float2 r;
    asm("mov.b64 {%0, %1}, %2;" : "=f"(r.x), "=f"(r.y) : "l"(v));
    return r;
}
__device__ __forceinline__ void stcg2(float* p, float x, float y) {
    asm volatile("st.global.cg.v2.f32 [%0], {%1,%2};" :: "l"(p), "f"(x), "f"(y));
}

// fp16 Dekker split: x = h0 + h1 (+ O(2^-24)); pack token-pair (low = even tok)
__device__ __forceinline__ void split_pair(float a, float b,
                                           uint32_t& h0, uint32_t& h1) {
    __half ha = __float2half_rn(a);
    __half hb = __float2half_rn(b);
    float ra = a - __half2float(ha);
    float rb = b - __half2float(hb);
    __half2 p0 = __halves2half2(ha, hb);
    __half2 p1 = __floats2half2_rn(ra, rb);
    h0 = *(uint32_t*)&p0;
    h1 = *(uint32_t*)&p1;
}

// m16n8k16 fp16 HMMA: D(f32) += A(f16) x B(f16)
__device__ __forceinline__ void mma16(float* d, const uint32_t* a, const uint32_t* b) {
    asm volatile(
        "mma.sync.aligned.m16n8k16.row.col.f32.f16.f16.f32 "
        "{%0,%1,%2,%3}, {%4,%5,%6,%7}, {%8,%9}, {%0,%1,%2,%3};"
        : "+f"(d[0]), "+f"(d[1]), "+f"(d[2]), "+f"(d[3])
        : "r"(a[0]), "r"(a[1]), "r"(a[2]), "r"(a[3]), "r"(b[0]), "r"(b[1]));
}

// ---------------------------------------------------------------------------
// Kernel A: partial kv_mul on fp16 HMMA (m16n8k16, 3-product Dekker split).
// kv[c][d] = sum_t K[t][c] * V[t][d];  A = K^T (m=c), B = V (n=d), k = t.
// Staging converts fp32 -> (h0,h1) half2 planes packed by token PAIR:
//   KH0[tp][c] = {h0(K[2tp][c]), h0(K[2tp+1][c])}   (u32 = half2)
// which is exactly the k-pair layout m16n8k16 fragments want -> the MMA loop
// is pure LDS.32 (conflict-free, RPH=72) + HMMA, zero conversion.
// 256 threads = 8 warps in 4(c) x 2(d) grid; warp tile 16c x 32d = acc[4][4].
// Per 16-token chunk/warp: 8 A-LDS + 16 B-LDS + 12 HMMAs {hh, hl, lh}.
// LDG.128 -> regs -> convert -> STS.128 double buffer, 32-token stages.
// ---------------------------------------------------------------------------
__global__ __launch_bounds__(256, 2) void kv_partial_kernel(
    const float* __restrict__ Kg, const float* __restrict__ Vg)
{
    extern __shared__ __align__(16) uint32_t su[];

    const int b   = blockIdx.y;
    const int sp  = blockIdx.x;
    const int tid = threadIdx.x;
    const int w   = tid >> 5;
    const int l   = tid & 31;
    const int lr  = l & 3;          // tid-in-group (k dimension)
    const int lq  = l >> 2;         // group id     (m / n dimension)
    const int c0  = (w & 3) * 16;   // warp c origin
    const int d0  = (w >> 2) * 32;  // warp d origin

    // staging: thread handles token-pair tp at 16B chunk c4 for K and V
    const int tp  = tid >> 4;       // 0..15
    const int c4  = tid & 15;
    const int goff = (2 * tp) * C + c4 * 4;      // token 2tp ; +C -> 2tp+1
    const int dstu = tp * RPH + c4 * 4;          // u32 offset within plane

    const float* Kbase = Kg + ((size_t)b * TOK + (size_t)sp * TPS) * C;
    const float* Vbase = Vg + ((size_t)b * TOK + (size_t)sp * TPS) * C;

    float4 pf[4];   // K(2tp), K(2tp+1), V(2tp), V(2tp+1)

    // convert+store one stage of this thread's data into buffer `bu`
    auto stash = [&](uint32_t* bu) {
        uint32_t kh0[4], kh1[4], vh0[4], vh1[4];
        const float* ka = (const float*)&pf[0];
        const float* kb = (const float*)&pf[1];
        const float* va = (const float*)&pf[2];
        const float* vb = (const float*)&pf[3];
        #pragma unroll
        for (int j = 0; j < 4; ++j) {
            split_pair(ka[j], kb[j], kh0[j], kh1[j]);
            split_pair(va[j], vb[j], vh0[j], vh1[j]);
        }
        *(uint4*)&bu[dstu]              = *(uint4*)kh0;
        *(uint4*)&bu[PLANEU + dstu]     = *(uint4*)kh1;
        *(uint4*)&bu[2 * PLANEU + dstu] = *(uint4*)vh0;
        *(uint4*)&bu[3 * PLANEU + dstu] = *(uint4*)vh1;
    };

    // prologue: stage 0 -> regs -> buf0 ; stage 1 -> regs
    pf[0] = *(const float4*)(Kbase + goff);
    pf[1] = *(const float4*)(Kbase + goff + C);
    pf[2] = *(const float4*)(Vbase + goff);
    pf[3] = *(const float4*)(Vbase + goff + C);
    stash(su);
    pf[0] = *(const float4*)(Kbase + goff + STAGE_T * C);
    pf[1] = *(const float4*)(Kbase + goff + STAGE_T * C + C);
    pf[2] = *(const float4*)(Vbase + goff + STAGE_T * C);
    pf[3] = *(const float4*)(Vbase + goff + STAGE_T * C + C);
    __syncthreads();

    float acc[4][4];                 // [n-chunk][frag reg]
    #pragma unroll
    for (int i = 0; i < 4; ++i)
        #pragma unroll
        for (int j = 0; j < 4; ++j) acc[i][j] = 0.f;

    #pragma unroll 1
    for (int it = 0; it < NSTAGES; ++it) {
        // stash stage it+1 into the buffer freed by stage it-1
        if (it + 1 < NSTAGES) stash(&su[((it + 1) & 1) * BUFU]);
        // prefetch stage it+2 into regs
        if (it + 2 < NSTAGES) {
            const int adv = (it + 2) * STAGE_T * C;
            pf[0] = *(const float4*)(Kbase + goff + adv);
            pf[1] = *(const float4*)(Kbase + goff + adv + C);
            pf[2] = *(const float4*)(Vbase + goff + adv);
            pf[3] = *(const float4*)(Vbase + goff + adv + C);
        }

        const uint32_t* kh0p = &su[(it & 1) * BUFU];
        const uint32_t* kh1p = kh0p + PLANEU;
        const uint32_t* vh0p = kh0p + 2 * PLANEU;
        const uint32_t* vh1p = kh0p + 3 * PLANEU;

        #pragma unroll
        for (int ch = 0; ch < 2; ++ch) {
            const int ra = (ch * 8 + lr) * RPH;       // k = 2lr, 2lr+1
            const int rb = (ch * 8 + lr + 4) * RPH;   // k = 2lr+8, 2lr+9
            uint32_t ah0[4], ah1[4];
            ah0[0] = kh0p[ra + c0 + lq];
            ah0[1] = kh0p[ra + c0 + lq + 8];
            ah0[2] = kh0p[rb + c0 + lq];
            ah0[3] = kh0p[rb + c0 + lq + 8];
            ah1[0] = kh1p[ra + c0 + lq];
            ah1[1] = kh1p[ra + c0 + lq + 8];
            ah1[2] = kh1p[rb + c0 + lq];
            ah1[3] = kh1p[rb + c0 + lq + 8];
            #pragma unroll
            for (int nn = 0; nn < 4; ++nn) {
                const int col = d0 + nn * 8 + lq;
                uint32_t bh0[2], bh1[2];
                bh0[0] = vh0p[ra + col];
                bh0[1] = vh0p[rb + col];
                bh1[0] = vh1p[ra + col];
                bh1[1] = vh1p[rb + col];
                mma16(acc[nn], ah0, bh0);
                mma16(acc[nn], ah0, bh1);
                mma16(acc[nn], ah1, bh0);
            }
        }
        __syncthreads();   // compute of it done everywhere; STS of it+1 drained
    }

    // epilogue: C fragment -> g_partial[b][sp][c][d]  (disjoint per warp)
    float* outp = &g_partial[((size_t)(b * SPLITS + sp)) * (C * C)];
    const int row0 = c0 + lq;
    const int row1 = row0 + 8;
    #pragma unroll
    for (int nn = 0; nn < 4; ++nn) {
        const int col = d0 + nn * 8 + 2 * lr;
        stcg2(&outp[row0 * C + col], acc[nn][0], acc[nn][1]);
        stcg2(&outp[row1 * C + col], acc[nn][2], acc[nn][3]);
    }
}

// ---------------------------------------------------------------------------
// Kernel B: deterministic split reduction (float4, fixed order).
// ---------------------------------------------------------------------------
__global__ __launch_bounds__(128, 1) void kv_reduce_kernel()
{
    int q = blockIdx.x * 128 + threadIdx.x;   // 0..4095 float4 index
    int b  = q >> 10;
    int e4 = q & 1023;
    const float4* p = (const float4*)&g_partial[(size_t)b * SPLITS * (C * C)] + e4;
    float4 s0 = make_float4(0.f,0.f,0.f,0.f), s1 = s0, s2 = s0, s3 = s0;
    float4 s4 = s0, s5 = s0, s6 = s0, s7 = s0;
    #pragma unroll 2
    for (int i = 0; i < SPLITS; i += 8) {
        float4 t0 = p[(size_t)(i    ) * 1024];
        float4 t1 = p[(size_t)(i + 1) * 1024];
        float4 t2 = p[(size_t)(i + 2) * 1024];
        float4 t3 = p[(size_t)(i + 3) * 1024];
        float4 t4 = p[(size_t)(i + 4) * 1024];
        float4 t5 = p[(size_t)(i + 5) * 1024];
        float4 t6 = p[(size_t)(i + 6) * 1024];
        float4 t7 = p[(size_t)(i + 7) * 1024];
        s0.x += t0.x; s0.y += t0.y; s0.z += t0.z; s0.w += t0.w;
        s1.x += t1.x; s1.y += t1.y; s1.z += t1.z; s1.w += t1.w;
        s2.x += t2.x; s2.y += t2.y; s2.z += t2.z; s2.w += t2.w;
        s3.x += t3.x; s3.y += t3.y; s3.z += t3.z; s3.w += t3.w;
        s4.x += t4.x; s4.y += t4.y; s4.z += t4.z; s4.w += t4.w;
        s5.x += t5.x; s5.y += t5.y; s5.z += t5.z; s5.w += t5.w;
        s6.x += t6.x; s6.y += t6.y; s6.z += t6.z; s6.w += t6.w;
        s7.x += t7.x; s7.y += t7.y; s7.z += t7.z; s7.w += t7.w;
    }
    float4 r;
    r.x = ((s0.x + s1.x) + (s2.x + s3.x)) + ((s4.x + s5.x) + (s6.x + s7.x));
    r.y = ((s0.y + s1.y) + (s2.y + s3.y)) + ((s4.y + s5.y) + (s6.y + s7.y));
    r.z = ((s0.z + s1.z) + (s2.z + s3.z)) + ((s4.z + s5.z) + (s6.z + s7.z));
    r.w = ((s0.w + s1.w) + (s2.w + s3.w)) + ((s4.w + s5.w) + (s6.w + s7.w));
    ((float4*)g_kv)[q] = r;
}

// ---------------------------------------------------------------------------
// Kernel C: softmax over the C axis (column-strided), alpha folded in.
// ---------------------------------------------------------------------------
__global__ void softmax_kernel(const float* __restrict__ alpha)
{
    int tid = threadIdx.x;
    int b = tid >> 6;
    int d = tid & 63;
    const float* in  = &g_kv[b * (C * C) + d];
    float*       out = &g_sm[b * (C * C) + d];

    float v[C];
    float m = -3.402823466e38f;
    #pragma unroll
    for (int c = 0; c < C; ++c) { v[c] = in[c * C]; m = fmaxf(m, v[c]); }
    float sum = 0.f;
    #pragma unroll
    for (int c = 0; c < C; ++c) { v[c] = expf(v[c] - m); sum += v[c]; }
    float sc = alpha[0] / sum;
    #pragma unroll
    for (int c = 0; c < C; ++c) out[c * C] = v[c] * sc;
}

// ---------------------------------------------------------------------------
// Kernel D: out[b,r,d] = sum_c key_cur[b,r,c] * sm[b,c,d] + val_cur.
// (round-6/9 proven: 128 thr, 128 rows/block, 8 rows x 8 d per thread)
// ---------------------------------------------------------------------------
__global__ __launch_bounds__(128, 2) void out_kernel(
    const float* __restrict__ key_cur, const float* __restrict__ val_cur,
    float* __restrict__ out)
{
    extern __shared__ __align__(16) float s[];
    float* s_sm  = s;                 // [c][d] 64x64, 16 KB
    float* s_key = s + C * C;         // [128][RP]

    const int b   = blockIdx.y;
    const int rb  = blockIdx.x;       // 0..127 (128 rows each)
    const int tid = threadIdx.x;
    const size_t row_base = (size_t)b * NROWS + (size_t)rb * 128;

    const float* smg = &g_sm[b * (C * C)];
    #pragma unroll
    for (int j = 0; j < 8; ++j) {
        int q = j * 128 + tid;
        *(float4*)&s_sm[q * 4] = *(const float4*)&smg[q * 4];
    }
    #pragma unroll
    for (int j = 0; j < 16; ++j) {
        int ch  = j * 128 + tid;
        int row = ch >> 4, c4 = ch & 15;
        *(float4*)&s_key[row * RP + c4 * 4] =
            *(const float4*)&key_cur[(row_base + row) * C + c4 * 4];
    }
    __syncthreads();

    const int rg = tid >> 3;          // rows rg, rg+16, ..., rg+112
    const int d0 = (tid & 7) * 8;

    u64 acc[8][4];
    #pragma unroll
    for (int i = 0; i < 8; ++i)
        #pragma unroll
        for (int p = 0; p < 4; ++p) acc[i][p] = 0ull;

    #pragma unroll 2
    for (int cq = 0; cq < 16; ++cq) {
        float4 kq[8];
        #pragma unroll
        for (int i = 0; i < 8; ++i)
            kq[i] = *(const float4*)&s_key[(rg + 16 * i) * RP + cq * 4];
        #pragma unroll
        for (int cc = 0; cc < 4; ++cc) {
            ulonglong2 sa = *(const ulonglong2*)&s_sm[(cq * 4 + cc) * C + d0];
            ulonglong2 sbv = *(const ulonglong2*)&s_sm[(cq * 4 + cc) * C + d0 + 4];
            #pragma unroll
            for (int i = 0; i < 8; ++i) {
                float kc = (cc == 0) ? kq[i].x : (cc == 1) ? kq[i].y
                         : (cc == 2) ? kq[i].z : kq[i].w;
                u64 kd;
                asm("mov.b64 %0, {%1, %1};" : "=l"(kd) : "f"(kc));
                acc[i][0] = fma2(kd, sa.x, acc[i][0]);
                acc[i][1] = fma2(kd, sa.y, acc[i][1]);
                acc[i][2] = fma2(kd, sbv.x, acc[i][2]);
                acc[i][3] = fma2(kd, sbv.y, acc[i][3]);
            }
        }
    }

    #pragma unroll
    for (int i = 0; i < 8; ++i) {
        size_t base = (row_base + rg + 16 * i) * C + d0;
        float4 v0 = *(const float4*)&val_cur[base];
        float4 v1 = *(const float4*)&val_cur[base + 4];
        float2 p0 = unpack2(acc[i][0]), p1 = unpack2(acc[i][1]);
        float2 p2 = unpack2(acc[i][2]), p3 = unpack2(acc[i][3]);
        *(float4*)&out[base]     = make_float4(p0.x + v0.x, p0.y + v0.y,
                                               p1.x + v0.z, p1.y + v0.w);
        *(float4*)&out[base + 4] = make_float4(p2.x + v1.x, p2.y + v1.y,
                                               p3.x + v1.z, p3.y + v1.w);
    }
}

// ---------------------------------------------------------------------------
extern "C" void kernel_launch(void* const* d_in, const int* in_sizes, int n_in,
                              void* d_out, int out_size)
{
    const float* key_mem = (const float*)d_in[0];
    const float* val_mem = (const float*)d_in[1];
    const float* key_cur = (const float*)d_in[2];
    const float* val_cur = (const float*)d_in[3];
    const float* alpha   = (const float*)d_in[4];
    float* out = (float*)d_out;

    cudaFuncSetAttribute(kv_partial_kernel,
                         cudaFuncAttributeMaxDynamicSharedMemorySize, KV_SMEM_BYTES);
    cudaFuncSetAttribute(out_kernel,
                         cudaFuncAttributeMaxDynamicSharedMemorySize, OUT_SMEM_BYTES);

    kv_partial_kernel<<<dim3(SPLITS, NB), 256, KV_SMEM_BYTES>>>(key_mem, val_mem);
    kv_reduce_kernel<<<32, 128>>>();
    softmax_kernel<<<1, 256>>>(alpha);
    out_kernel<<<dim3(NROWS / 128, NB), 128, OUT_SMEM_BYTES>>>(key_cur, val_cur, out);
}